// round 1
// baseline (speedup 1.0000x reference)
#include <cuda_runtime.h>
#include <math.h>

// Problem constants
constexpr int Sdim = 2048;
constexpr int Ddim = 64;
constexpr int Hdim = 16;
constexpr int BHdim = 64;        // B*H
constexpr int TQ   = 16;         // query rows per block
constexpr int TKS  = 256;        // key slab per smem pass
constexpr int NSLAB = Sdim / TKS;

// smem strides (floats), padded for bank-conflict-free access
constexpr int SC_STRIDE = 2052;  // 2048 + 4  (row byte offset 8208 ≡ 0 mod 16, bank shift 4)
constexpr int QS_STRIDE = 65;
constexpr int KV_STRIDE = 68;    // multiple of 4 -> float4-aligned rows, odd/4 pattern kills conflicts

constexpr int SC_OFF = 0;
constexpr int QS_OFF = TQ * SC_STRIDE;            // 32832
constexpr int KV_OFF = QS_OFF + TQ * QS_STRIDE;   // 33872
constexpr int PM_OFF = KV_OFF + TKS * KV_STRIDE;  // 51280
constexpr int SMEM_FLOATS = PM_OFF + TKS;         // pm (int) shares 4B slots
constexpr size_t SMEM_BYTES = (size_t)SMEM_FLOATS * 4;  // 206,144 B

__device__ __forceinline__ float warp_max(float v) {
    #pragma unroll
    for (int o = 16; o > 0; o >>= 1) v = fmaxf(v, __shfl_xor_sync(0xffffffffu, v, o));
    return v;
}
__device__ __forceinline__ float warp_sum(float v) {
    #pragma unroll
    for (int o = 16; o > 0; o >>= 1) v += __shfl_xor_sync(0xffffffffu, v, o);
    return v;
}

__global__ __launch_bounds__(256, 1)
void attn_kernel(const float* __restrict__ Q, const float* __restrict__ K,
                 const float* __restrict__ V, const int* __restrict__ pad,
                 float* __restrict__ outO, float* __restrict__ outW, int writeW)
{
    extern __shared__ float smem[];
    float* sc = smem + SC_OFF;          // [TQ][SC_STRIDE]
    float* qs = smem + QS_OFF;          // [TQ][QS_STRIDE]
    float* kv = smem + KV_OFF;          // [TKS][KV_STRIDE]
    int*   pm = (int*)(smem + PM_OFF);  // [TKS]
    float* red = kv;                    // reused after PV mainloop

    const int tid = threadIdx.x;
    const int bh  = blockIdx.y;
    const int q0  = blockIdx.x * TQ;
    const int b   = bh / Hdim;

    const float* Qb = Q + ((size_t)bh * Sdim + q0) * Ddim;
    const float* Kb = K + (size_t)bh * Sdim * Ddim;
    const float* Vb = V + (size_t)bh * Sdim * Ddim;
    const int*   pb = pad + (size_t)b * Sdim;

    // ---- load Q tile into smem ----
    for (int i = tid; i < TQ * Ddim; i += 256) {
        int q = i >> 6, d = i & 63;
        qs[q * QS_STRIDE + d] = Qb[q * Ddim + d];
    }

    // ======================= QK^T phase =======================
    // mapping: qg = tid&3 (q = qg + 4j), kg = tid>>2 (k = kg + 64j)
    const int qg = tid & 3;
    const int kg = tid >> 2;

    for (int s = 0; s < NSLAB; ++s) {
        const int k0 = s * TKS;
        __syncthreads();  // prev compute done before overwriting kv (also covers qs on s==0)
        // load K slab [TKS][D] (float4 coalesced)
        for (int i = tid; i < TKS * (Ddim / 4); i += 256) {
            int row = i >> 4;
            int c   = (i & 15) << 2;
            *(float4*)&kv[row * KV_STRIDE + c] =
                *(const float4*)&Kb[(size_t)(k0 + row) * Ddim + c];
        }
        pm[tid] = pb[k0 + tid];
        __syncthreads();

        float acc[4][4];
        #pragma unroll
        for (int a = 0; a < 4; ++a)
            #pragma unroll
            for (int c = 0; c < 4; ++c) acc[a][c] = 0.f;

        #pragma unroll 8
        for (int d = 0; d < Ddim; ++d) {
            float kr[4], qr[4];
            #pragma unroll
            for (int j = 0; j < 4; ++j) {
                kr[j] = kv[(kg + 64 * j) * KV_STRIDE + d];
                qr[j] = qs[(qg + 4 * j) * QS_STRIDE + d];
            }
            #pragma unroll
            for (int jq = 0; jq < 4; ++jq)
                #pragma unroll
                for (int jk = 0; jk < 4; ++jk)
                    acc[jq][jk] = fmaf(qr[jq], kr[jk], acc[jq][jk]);
        }

        // scale + faithful mask ((future + pad) == 1 -> -1e9), store to score strip
        #pragma unroll
        for (int jq = 0; jq < 4; ++jq) {
            const int q     = qg + 4 * jq;
            const int qglob = q0 + q;
            #pragma unroll
            for (int jk = 0; jk < 4; ++jk) {
                const int kloc  = kg + 64 * jk;
                const int kglob = k0 + kloc;
                const int comb  = ((kglob > qglob) ? 1 : 0) + pm[kloc];
                const float val = (comb == 1) ? -1e9f : acc[jq][jk] * 0.125f;
                sc[q * SC_STRIDE + k0 + kloc] = val;
            }
        }
    }
    __syncthreads();

    // ======================= softmax phase =======================
    {
        const int warp = tid >> 5;
        const int lane = tid & 31;
        for (int r = 0; r < 2; ++r) {
            const int q = warp * 2 + r;
            float* row = sc + q * SC_STRIDE;
            float4* row4 = (float4*)row;

            float m = -INFINITY;
            for (int i = lane; i < Sdim / 4; i += 32) {
                float4 v = row4[i];
                m = fmaxf(m, fmaxf(fmaxf(v.x, v.y), fmaxf(v.z, v.w)));
            }
            m = warp_max(m);

            float ssum = 0.f;
            for (int i = lane; i < Sdim / 4; i += 32) {
                float4 v = row4[i];
                v.x = __expf(v.x - m); v.y = __expf(v.y - m);
                v.z = __expf(v.z - m); v.w = __expf(v.w - m);
                row4[i] = v;
                ssum += (v.x + v.y) + (v.z + v.w);
            }
            ssum = warp_sum(ssum);
            const float inv = 1.0f / ssum;

            float4* wrow4 = nullptr;
            if (writeW)
                wrow4 = (float4*)(outW + ((size_t)bh * Sdim + (q0 + q)) * Sdim);
            for (int i = lane; i < Sdim / 4; i += 32) {
                float4 v = row4[i];
                v.x *= inv; v.y *= inv; v.z *= inv; v.w *= inv;
                row4[i] = v;
                if (writeW) wrow4[i] = v;
            }
        }
    }
    __syncthreads();

    // ======================= P @ V phase =======================
    // mapping: dg = tid&15 (d = 4*dg..), qg2 = (tid>>4)&3 (q = 4*qg2+j), kp = tid>>6 (k partial)
    const int dg  = tid & 15;
    const int qg2 = (tid >> 4) & 3;
    const int kp  = tid >> 6;

    float4 acc2[4];
    #pragma unroll
    for (int j = 0; j < 4; ++j) acc2[j] = make_float4(0.f, 0.f, 0.f, 0.f);

    for (int s = 0; s < NSLAB; ++s) {
        const int k0 = s * TKS;
        __syncthreads();
        for (int i = tid; i < TKS * (Ddim / 4); i += 256) {
            int row = i >> 4;
            int c   = (i & 15) << 2;
            *(float4*)&kv[row * KV_STRIDE + c] =
                *(const float4*)&Vb[(size_t)(k0 + row) * Ddim + c];
        }
        __syncthreads();

        #pragma unroll 4
        for (int ks = 0; ks < TKS / 4; ++ks) {
            const int k = ks * 4 + kp;
            const float4 v = *(const float4*)&kv[k * KV_STRIDE + 4 * dg];
            #pragma unroll
            for (int j = 0; j < 4; ++j) {
                const float w = sc[(4 * qg2 + j) * SC_STRIDE + k0 + k];
                acc2[j].x = fmaf(w, v.x, acc2[j].x);
                acc2[j].y = fmaf(w, v.y, acc2[j].y);
                acc2[j].z = fmaf(w, v.z, acc2[j].z);
                acc2[j].w = fmaf(w, v.w, acc2[j].w);
            }
        }
    }
    __syncthreads();

    // cross k-partial reduction through smem (reuse kv region)
    #pragma unroll
    for (int j = 0; j < 4; ++j)
        *(float4*)&red[tid * 16 + j * 4] = acc2[j];
    __syncthreads();

    if (tid < 64) {
        const int dgo = tid & 15;
        const int qgo = tid >> 4;
        #pragma unroll
        for (int j = 0; j < 4; ++j) {
            float4 a = *(float4*)&red[tid * 16 + j * 4];
            #pragma unroll
            for (int p = 1; p < 4; ++p) {
                float4 t = *(float4*)&red[(tid + 64 * p) * 16 + j * 4];
                a.x += t.x; a.y += t.y; a.z += t.z; a.w += t.w;
            }
            const int q = q0 + 4 * qgo + j;
            *(float4*)&outO[((size_t)bh * Sdim + q) * Ddim + 4 * dgo] = a;
        }
    }
}

extern "C" void kernel_launch(void* const* d_in, const int* in_sizes, int n_in,
                              void* d_out, int out_size)
{
    const float* Q   = (const float*)d_in[0];
    const float* K   = (const float*)d_in[1];
    const float* V   = (const float*)d_in[2];
    const int*   pad = (const int*)d_in[3];

    const long long nres = (long long)BHdim * Sdim * Ddim;          // 8,388,608
    const long long nw   = (long long)BHdim * Sdim * Sdim;          // 268,435,456
    const int writeW = ((long long)out_size >= nres + nw) ? 1 : 0;

    float* outO = (float*)d_out;
    float* outW = writeW ? (outO + nres) : outO;

    cudaFuncSetAttribute(attn_kernel, cudaFuncAttributeMaxDynamicSharedMemorySize,
                         (int)SMEM_BYTES);

    dim3 grid(Sdim / TQ, BHdim);
    attn_kernel<<<grid, 256, SMEM_BYTES>>>(Q, K, V, pad, outO, outW, writeW);
}

// round 2
// speedup vs baseline: 1.4864x; 1.4864x over previous
#include <cuda_runtime.h>
#include <math.h>

// Problem constants
constexpr int Sdim  = 2048;
constexpr int Ddim  = 64;
constexpr int Hdim  = 16;
constexpr int BHdim = 64;        // B*H
constexpr int TQ    = 32;        // query rows per block
constexpr int TKS   = 256;       // key slab per smem pass
constexpr int NSLAB = Sdim / TKS;

// smem strides (floats)
constexpr int KV_STRIDE = 68;    // 64 + 4, float4-aligned, conflict-free
constexpr int QS_STRIDE = 65;
constexpr int ES_STRIDE = 260;   // 256 + 4, float4-aligned
constexpr int RED_STRIDE = 36;   // per-thread reduction stride (float4-aligned, bank-shifted)

constexpr int KV_OFF  = 0;                        // K/V slab: 256*68 = 17408 floats
constexpr int RS_OFF  = TKS * KV_STRIDE;          // rowsum[32]
constexpr int INV_OFF = RS_OFF + TQ;              // inv[32]
constexpr int U_OFF   = INV_OFF + TQ;             // union region (QK: qs+pm / PV: es)
constexpr int QS_OFF  = U_OFF;                    // 32*65 = 2080 floats
constexpr int PM_OFF  = QS_OFF + TQ * QS_STRIDE;  // 256 ints
constexpr int ES_OFF  = U_OFF;                    // 32*260 = 8320 floats
constexpr int SMEM_FLOATS = U_OFF + TQ * ES_STRIDE;
constexpr size_t SMEM_BYTES = (size_t)SMEM_FLOATS * 4;   // 103,168 B -> 2 CTAs/SM

__global__ __launch_bounds__(256, 2)
void attn_kernel(const float* __restrict__ Q, const float* __restrict__ K,
                 const float* __restrict__ V, const int* __restrict__ pad,
                 float* __restrict__ outO, float* __restrict__ outW)
{
    extern __shared__ float smem[];
    float* kv     = smem + KV_OFF;
    float* rowsum = smem + RS_OFF;
    float* inv    = smem + INV_OFF;
    float* qs     = smem + QS_OFF;
    int*   pm     = (int*)(smem + PM_OFF);
    float* es     = smem + ES_OFF;
    float* red    = kv;              // reused after PV mainloop

    const int tid = threadIdx.x;
    const int bh  = blockIdx.y;
    const int q0  = blockIdx.x * TQ;
    const int b   = bh / Hdim;

    const float* Qb = Q + ((size_t)bh * Sdim + q0) * Ddim;
    const float* Kb = K + (size_t)bh * Sdim * Ddim;
    const float* Vb = V + (size_t)bh * Sdim * Ddim;
    const int*   pb = pad + (size_t)b * Sdim;
    float* Wbase = outW + ((size_t)bh * Sdim + q0) * Sdim;  // [TQ][Sdim]

    // ---- load Q tile, zero rowsums ----
    for (int i = tid; i < TQ * Ddim; i += 256) {
        int q = i >> 6, d = i & 63;
        qs[q * QS_STRIDE + d] = Qb[q * Ddim + d];
    }
    if (tid < TQ) rowsum[tid] = 0.f;

    // ======================= QK^T + exp phase =======================
    // thread tile: 8 q (q = qg + 4*jq) x 4 k (k = kg + 64*jk), qg = tid&3, kg = tid>>2
    const int qg = tid & 3;
    const int kg = tid >> 2;

    float rsum[8];
    #pragma unroll
    for (int j = 0; j < 8; ++j) rsum[j] = 0.f;

    for (int s = 0; s < NSLAB; ++s) {
        const int k0 = s * TKS;
        __syncthreads();  // protect kv/pm from prev iter; covers qs/rowsum init on s==0
        for (int i = tid; i < TKS * (Ddim / 4); i += 256) {
            int row = i >> 4;
            int c   = (i & 15) << 2;
            *(float4*)&kv[row * KV_STRIDE + c] =
                *(const float4*)&Kb[(size_t)(k0 + row) * Ddim + c];
        }
        pm[tid] = pb[k0 + tid];
        __syncthreads();

        float acc[8][4];
        #pragma unroll
        for (int a = 0; a < 8; ++a)
            #pragma unroll
            for (int c = 0; c < 4; ++c) acc[a][c] = 0.f;

        #pragma unroll 4
        for (int d = 0; d < Ddim; ++d) {
            float kr[4], qr[8];
            #pragma unroll
            for (int j = 0; j < 4; ++j) kr[j] = kv[(kg + 64 * j) * KV_STRIDE + d];
            #pragma unroll
            for (int j = 0; j < 8; ++j) qr[j] = qs[(qg + 4 * j) * QS_STRIDE + d];
            #pragma unroll
            for (int jq = 0; jq < 8; ++jq)
                #pragma unroll
                for (int jk = 0; jk < 4; ++jk)
                    acc[jq][jk] = fmaf(qr[jq], kr[jk], acc[jq][jk]);
        }

        // epilogue: faithful mask ((future + pad) == 1 -> masked), exp, write e, row sums
        #pragma unroll
        for (int jq = 0; jq < 8; ++jq) {
            const int q     = qg + 4 * jq;
            const int qglob = q0 + q;
            float* wr = Wbase + (size_t)q * Sdim + k0;
            #pragma unroll
            for (int jk = 0; jk < 4; ++jk) {
                const int kloc  = kg + 64 * jk;
                const int comb  = (((k0 + kloc) > qglob) ? 1 : 0) + pm[kloc];
                const float e   = (comb == 1) ? 0.f : __expf(acc[jq][jk] * 0.125f);
                wr[kloc] = e;
                rsum[jq] += e;
            }
        }
    }

    // reduce row sums: within warp over kg lanes (bits 2..4 of lane), then smem atomics
    #pragma unroll
    for (int jq = 0; jq < 8; ++jq) {
        #pragma unroll
        for (int o = 4; o <= 16; o <<= 1)
            rsum[jq] += __shfl_xor_sync(0xffffffffu, rsum[jq], o);
    }
    if ((tid & 31) < 4) {  // lane 0..3 holds totals for qg = lane&3
        #pragma unroll
        for (int jq = 0; jq < 8; ++jq)
            atomicAdd(&rowsum[(tid & 3) + 4 * jq], rsum[jq]);
    }
    __syncthreads();
    if (tid < TQ) inv[tid] = 1.0f / rowsum[tid];
    // (visibility of inv guaranteed by the syncthreads at top of PV loop)

    // ======================= P @ V phase =======================
    // thread tile: dg = tid&15 (4 d-cols), qg2 = (tid>>4)&3 (8 q rows), kp = tid>>6 (k partial)
    const int dg  = tid & 15;
    const int qg2 = (tid >> 4) & 3;
    const int kp  = tid >> 6;

    float4 acc2[8];
    #pragma unroll
    for (int j = 0; j < 8; ++j) acc2[j] = make_float4(0.f, 0.f, 0.f, 0.f);

    for (int s = 0; s < NSLAB; ++s) {
        const int k0 = s * TKS;
        __syncthreads();
        // V slab
        for (int i = tid; i < TKS * (Ddim / 4); i += 256) {
            int row = i >> 4;
            int c   = (i & 15) << 2;
            *(float4*)&kv[row * KV_STRIDE + c] =
                *(const float4*)&Vb[(size_t)(k0 + row) * Ddim + c];
        }
        // e slab: read unnormalized e from gmem, normalize, stage to smem + write final W
        for (int i = tid; i < TQ * (TKS / 4); i += 256) {
            int q = i >> 6;
            int c = (i & 63) << 2;
            float* gw = Wbase + (size_t)q * Sdim + k0 + c;
            float4 e4 = *(float4*)gw;
            const float iv = inv[q];
            e4.x *= iv; e4.y *= iv; e4.z *= iv; e4.w *= iv;
            *(float4*)&es[q * ES_STRIDE + c] = e4;
            *(float4*)gw = e4;
        }
        __syncthreads();

        #pragma unroll 4
        for (int ks = 0; ks < TKS / 4; ++ks) {
            const int k = ks * 4 + kp;
            const float4 v = *(const float4*)&kv[k * KV_STRIDE + 4 * dg];
            #pragma unroll
            for (int j = 0; j < 8; ++j) {
                const float w = es[(qg2 * 8 + j) * ES_STRIDE + k];
                acc2[j].x = fmaf(w, v.x, acc2[j].x);
                acc2[j].y = fmaf(w, v.y, acc2[j].y);
                acc2[j].z = fmaf(w, v.z, acc2[j].z);
                acc2[j].w = fmaf(w, v.w, acc2[j].w);
            }
        }
    }
    __syncthreads();

    // cross k-partial reduction through smem (reuse kv region)
    #pragma unroll
    for (int j = 0; j < 8; ++j)
        *(float4*)&red[tid * RED_STRIDE + j * 4] = acc2[j];
    __syncthreads();

    if (tid < 64) {
        const int dgo = tid & 15;
        const int qgo = tid >> 4;   // 0..3
        #pragma unroll
        for (int j = 0; j < 8; ++j) {
            float4 a = *(float4*)&red[tid * RED_STRIDE + j * 4];
            #pragma unroll
            for (int p = 1; p < 4; ++p) {
                float4 t = *(float4*)&red[(tid + 64 * p) * RED_STRIDE + j * 4];
                a.x += t.x; a.y += t.y; a.z += t.z; a.w += t.w;
            }
            const int q = q0 + qgo * 8 + j;
            *(float4*)&outO[((size_t)bh * Sdim + q) * Ddim + 4 * dgo] = a;
        }
    }
}

extern "C" void kernel_launch(void* const* d_in, const int* in_sizes, int n_in,
                              void* d_out, int out_size)
{
    const float* Q   = (const float*)d_in[0];
    const float* K   = (const float*)d_in[1];
    const float* V   = (const float*)d_in[2];
    const int*   pad = (const int*)d_in[3];

    const long long nres = (long long)BHdim * Sdim * Ddim;   // 8,388,608
    float* outO = (float*)d_out;
    float* outW = outO + nres;   // out = (result, attention_weights), proven in round 1

    cudaFuncSetAttribute(attn_kernel, cudaFuncAttributeMaxDynamicSharedMemorySize,
                         (int)SMEM_BYTES);

    dim3 grid(Sdim / TQ, BHdim);
    attn_kernel<<<grid, 256, SMEM_BYTES>>>(Q, K, V, pad, outO, outW);
}

// round 3
// speedup vs baseline: 1.6746x; 1.1266x over previous
#include <cuda_runtime.h>
#include <math.h>

typedef unsigned long long u64;

// Problem constants
constexpr int Sdim  = 2048;
constexpr int Ddim  = 64;
constexpr int Hdim  = 16;
constexpr int BHdim = 64;        // B*H
constexpr int TQ    = 32;        // query rows per block
constexpr int TKS   = 256;       // key slab per smem pass
constexpr int NSLAB = Sdim / TKS;

// smem strides (floats)
constexpr int KV_STRIDE = 68;    // 64+4: float4-aligned rows, phase-conflict-free
constexpr int QS_STRIDE = 68;    // same property for Q rows
constexpr int ES_STRIDE = 260;   // 256+4, float4-aligned
constexpr int RED_STRIDE = 36;

constexpr int KV_OFF  = 0;                        // 256*68 = 17408 floats
constexpr int RS_OFF  = TKS * KV_STRIDE;
constexpr int INV_OFF = RS_OFF + TQ;
constexpr int U_OFF   = INV_OFF + TQ;
constexpr int QS_OFF  = U_OFF;                    // 32*68 = 2176
constexpr int PM_OFF  = QS_OFF + TQ * QS_STRIDE;  // 256 ints
constexpr int ES_OFF  = U_OFF;                    // 32*260 = 8320
constexpr int SMEM_FLOATS = U_OFF + TQ * ES_STRIDE;
constexpr size_t SMEM_BYTES = (size_t)SMEM_FLOATS * 4;   // ~103 KB -> 2 CTAs/SM

// ---- packed f32x2 helpers (sm_103a FFMA2 path) ----
__device__ __forceinline__ u64 pack2(float lo, float hi) {
    u64 r; asm("mov.b64 %0, {%1, %2};" : "=l"(r) : "f"(lo), "f"(hi)); return r;
}
__device__ __forceinline__ void unpack2(u64 v, float& lo, float& hi) {
    asm("mov.b64 {%0, %1}, %2;" : "=f"(lo), "=f"(hi) : "l"(v));
}
__device__ __forceinline__ u64 ffma2(u64 a, u64 b, u64 c) {
    u64 d; asm("fma.rn.f32x2 %0, %1, %2, %3;" : "=l"(d) : "l"(a), "l"(b), "l"(c)); return d;
}

__global__ __launch_bounds__(256, 2)
void attn_kernel(const float* __restrict__ Q, const float* __restrict__ K,
                 const float* __restrict__ V, const int* __restrict__ pad,
                 float* __restrict__ outO, float* __restrict__ outW)
{
    extern __shared__ float smem[];
    float* kv     = smem + KV_OFF;
    float* rowsum = smem + RS_OFF;
    float* inv    = smem + INV_OFF;
    float* qs     = smem + QS_OFF;
    int*   pm     = (int*)(smem + PM_OFF);
    float* es     = smem + ES_OFF;
    float* red    = kv;              // reused after PV mainloop

    const int tid = threadIdx.x;
    const int bh  = blockIdx.y;
    const int q0  = blockIdx.x * TQ;
    const int b   = bh / Hdim;

    const float* Qb = Q + ((size_t)bh * Sdim + q0) * Ddim;
    const float* Kb = K + (size_t)bh * Sdim * Ddim;
    const float* Vb = V + (size_t)bh * Sdim * Ddim;
    const int*   pb = pad + (size_t)b * Sdim;
    float* Wbase = outW + ((size_t)bh * Sdim + q0) * Sdim;  // [TQ][Sdim]

    // ---- load Q tile, zero rowsums ----
    for (int i = tid; i < TQ * Ddim; i += 256) {
        int q = i >> 6, d = i & 63;
        qs[q * QS_STRIDE + d] = Qb[q * Ddim + d];
    }
    if (tid < TQ) rowsum[tid] = 0.f;

    // ======================= QK^T + exp phase =======================
    // thread tile: 8 q (q = qg + 4*jq) x 4 k (k = kg + 64*jk)
    const int qg = tid & 3;
    const int kg = tid >> 2;

    float rsum[8];
    #pragma unroll
    for (int j = 0; j < 8; ++j) rsum[j] = 0.f;

    for (int s = 0; s < NSLAB; ++s) {
        const int k0 = s * TKS;
        __syncthreads();  // protect kv/pm from prev iter; covers qs/rowsum init on s==0
        for (int i = tid; i < TKS * (Ddim / 4); i += 256) {
            int row = i >> 4;
            int c   = (i & 15) << 2;
            *(float4*)&kv[row * KV_STRIDE + c] =
                *(const float4*)&Kb[(size_t)(k0 + row) * Ddim + c];
        }
        pm[tid] = pb[k0 + tid];
        __syncthreads();

        // packed accumulators: acc[jq][jk] = (sum over even d-sub, sum over odd d-sub)
        u64 acc[8][4];
        #pragma unroll
        for (int a = 0; a < 8; ++a)
            #pragma unroll
            for (int c = 0; c < 4; ++c) acc[a][c] = 0ull;

        for (int d4 = 0; d4 < Ddim; d4 += 4) {
            ulonglong2 kr2[4];
            #pragma unroll
            for (int jk = 0; jk < 4; ++jk)
                kr2[jk] = *(const ulonglong2*)&kv[(kg + 64 * jk) * KV_STRIDE + d4];
            #pragma unroll
            for (int jq = 0; jq < 8; ++jq) {
                const ulonglong2 qr2 =
                    *(const ulonglong2*)&qs[(qg + 4 * jq) * QS_STRIDE + d4];
                #pragma unroll
                for (int jk = 0; jk < 4; ++jk) {
                    acc[jq][jk] = ffma2(qr2.x, kr2[jk].x, acc[jq][jk]);
                    acc[jq][jk] = ffma2(qr2.y, kr2[jk].y, acc[jq][jk]);
                }
            }
        }

        // epilogue: faithful mask ((future + pad) == 1), exp, write e, row sums
        #pragma unroll
        for (int jq = 0; jq < 8; ++jq) {
            const int q     = qg + 4 * jq;
            const int qglob = q0 + q;
            float* wr = Wbase + (size_t)q * Sdim + k0;
            #pragma unroll
            for (int jk = 0; jk < 4; ++jk) {
                const int kloc = kg + 64 * jk;
                const int comb = (((k0 + kloc) > qglob) ? 1 : 0) + pm[kloc];
                float lo, hi; unpack2(acc[jq][jk], lo, hi);
                const float e = (comb == 1) ? 0.f : __expf((lo + hi) * 0.125f);
                wr[kloc] = e;
                rsum[jq] += e;
            }
        }
    }

    // reduce row sums: shuffle across kg-lanes, then smem atomics
    #pragma unroll
    for (int jq = 0; jq < 8; ++jq) {
        #pragma unroll
        for (int o = 4; o <= 16; o <<= 1)
            rsum[jq] += __shfl_xor_sync(0xffffffffu, rsum[jq], o);
    }
    if ((tid & 31) < 4) {
        #pragma unroll
        for (int jq = 0; jq < 8; ++jq)
            atomicAdd(&rowsum[(tid & 3) + 4 * jq], rsum[jq]);
    }
    __syncthreads();
    if (tid < TQ) inv[tid] = 1.0f / rowsum[tid];
    // (visibility of inv guaranteed by the syncthreads at top of PV loop)

    // ======================= P @ V phase =======================
    // thread tile: dg = tid&15 (4 d-cols), qg2 = (tid>>4)&3 (8 q rows), kp = tid>>6
    const int dg  = tid & 15;
    const int qg2 = (tid >> 4) & 3;
    const int kp  = tid >> 6;

    // packed accumulators over (even k, odd k): acc2[q][d]
    u64 acc2[8][4];
    #pragma unroll
    for (int j = 0; j < 8; ++j)
        #pragma unroll
        for (int d = 0; d < 4; ++d) acc2[j][d] = 0ull;

    for (int s = 0; s < NSLAB; ++s) {
        const int k0 = s * TKS;
        __syncthreads();
        // V slab
        for (int i = tid; i < TKS * (Ddim / 4); i += 256) {
            int row = i >> 4;
            int c   = (i & 15) << 2;
            *(float4*)&kv[row * KV_STRIDE + c] =
                *(const float4*)&Vb[(size_t)(k0 + row) * Ddim + c];
        }
        // e slab: read unnormalized e (L2-hot), normalize, stage to smem + write final W
        for (int i = tid; i < TQ * (TKS / 4); i += 256) {
            int q = i >> 6;
            int c = (i & 63) << 2;
            float* gw = Wbase + (size_t)q * Sdim + k0 + c;
            float4 e4 = *(float4*)gw;
            const float iv = inv[q];
            e4.x *= iv; e4.y *= iv; e4.z *= iv; e4.w *= iv;
            *(float4*)&es[q * ES_STRIDE + c] = e4;
            *(float4*)gw = e4;
        }
        __syncthreads();

        #pragma unroll 2
        for (int i = 0; i < TKS / 8; ++i) {
            const int k = 8 * i + 2 * kp;   // even
            const float4 va = *(const float4*)&kv[k * KV_STRIDE + 4 * dg];
            const float4 vb = *(const float4*)&kv[(k + 1) * KV_STRIDE + 4 * dg];
            u64 vp[4];
            vp[0] = pack2(va.x, vb.x);
            vp[1] = pack2(va.y, vb.y);
            vp[2] = pack2(va.z, vb.z);
            vp[3] = pack2(va.w, vb.w);
            #pragma unroll
            for (int j = 0; j < 8; ++j) {
                const u64 wp = *(const u64*)&es[(qg2 * 8 + j) * ES_STRIDE + k];
                #pragma unroll
                for (int d = 0; d < 4; ++d)
                    acc2[j][d] = ffma2(wp, vp[d], acc2[j][d]);
            }
        }
    }
    __syncthreads();

    // collapse k-even/odd pairs, cross k-partial reduction through smem
    #pragma unroll
    for (int j = 0; j < 8; ++j) {
        float4 a;
        float lo, hi;
        unpack2(acc2[j][0], lo, hi); a.x = lo + hi;
        unpack2(acc2[j][1], lo, hi); a.y = lo + hi;
        unpack2(acc2[j][2], lo, hi); a.z = lo + hi;
        unpack2(acc2[j][3], lo, hi); a.w = lo + hi;
        *(float4*)&red[tid * RED_STRIDE + j * 4] = a;
    }
    __syncthreads();

    if (tid < 64) {
        const int dgo = tid & 15;
        const int qgo = tid >> 4;   // 0..3
        #pragma unroll
        for (int j = 0; j < 8; ++j) {
            float4 a = *(float4*)&red[tid * RED_STRIDE + j * 4];
            #pragma unroll
            for (int p = 1; p < 4; ++p) {
                float4 t = *(float4*)&red[(tid + 64 * p) * RED_STRIDE + j * 4];
                a.x += t.x; a.y += t.y; a.z += t.z; a.w += t.w;
            }
            const int q = q0 + qgo * 8 + j;
            *(float4*)&outO[((size_t)bh * Sdim + q) * Ddim + 4 * dgo] = a;
        }
    }
}

extern "C" void kernel_launch(void* const* d_in, const int* in_sizes, int n_in,
                              void* d_out, int out_size)
{
    const float* Q   = (const float*)d_in[0];
    const float* K   = (const float*)d_in[1];
    const float* V   = (const float*)d_in[2];
    const int*   pad = (const int*)d_in[3];

    const long long nres = (long long)BHdim * Sdim * Ddim;   // 8,388,608
    float* outO = (float*)d_out;
    float* outW = outO + nres;   // out = (result, attention_weights)

    cudaFuncSetAttribute(attn_kernel, cudaFuncAttributeMaxDynamicSharedMemorySize,
                         (int)SMEM_BYTES);

    dim3 grid(Sdim / TQ, BHdim);
    attn_kernel<<<grid, 256, SMEM_BYTES>>>(Q, K, V, pad, outO, outW);
}

// round 5
// speedup vs baseline: 2.4681x; 1.4739x over previous
#include <cuda_runtime.h>
#include <cuda_bf16.h>
#include <stdint.h>

// ---------------- problem constants ----------------
constexpr int Sdim = 2048, Hdim = 16, BHdim = 64, Ddim = 64;
constexpr int TQ = 64;            // query rows per CTA
constexpr int NK = 128;           // key slab
constexpr int NSLAB = Sdim / NK;  // 16

// ---------------- smem layout (byte offsets) ----------------
// row strides: bf16 tiles 144B (64+8 elems, 16B-aligned, 8-row ldmatrix conflict-free),
// P tiles 272B (128+8 elems), EBUF f32 stride 132 elems.
constexpr int RS_B    = 0;       // f32[64] rowsum
constexpr int INV_B   = 256;     // f32[64]
constexpr int PM_B    = 512;     // int[128]
constexpr int QS_HI_B = 1024;    // [64][72] bf16 = 9216
constexpr int QS_LO_B = 10240;
constexpr int KS_HI_B = 19456;   // [128][72] bf16 = 18432  (V reuses in PV phase)
constexpr int KS_LO_B = 37888;
constexpr int EB_B    = 56320;   // f32 [64][132] = 33792   (QK phase)
constexpr int PS_HI_B = 56320;   // [64][136] bf16 = 17408  (PV phase, shares region)
constexpr int PS_LO_B = 73728;
constexpr int SMEM_TOTAL = 91136;   // 2 CTAs/SM (182KB < 228KB)

constexpr int QK_STR = 144;   // bytes per bf16 tile row (Q/K/V)
constexpr int PS_STR = 272;   // bytes per P tile row
constexpr int EB_STR = 132;   // floats per EBUF row

// ---------------- helpers ----------------
__device__ __forceinline__ uint32_t smem_u32(const void* p) {
    uint32_t a;
    asm("{ .reg .u64 t; cvta.to.shared.u64 t, %1; cvt.u32.u64 %0, t; }" : "=r"(a) : "l"(p));
    return a;
}
__device__ __forceinline__ void ldsm4(uint32_t addr, uint32_t& r0, uint32_t& r1,
                                      uint32_t& r2, uint32_t& r3) {
    asm volatile("ldmatrix.sync.aligned.m8n8.x4.shared.b16 {%0,%1,%2,%3}, [%4];"
                 : "=r"(r0), "=r"(r1), "=r"(r2), "=r"(r3) : "r"(addr));
}
__device__ __forceinline__ void ldsm4t(uint32_t addr, uint32_t& r0, uint32_t& r1,
                                       uint32_t& r2, uint32_t& r3) {
    asm volatile("ldmatrix.sync.aligned.m8n8.x4.trans.shared.b16 {%0,%1,%2,%3}, [%4];"
                 : "=r"(r0), "=r"(r1), "=r"(r2), "=r"(r3) : "r"(addr));
}
__device__ __forceinline__ void mma16816(float* c, uint32_t a0, uint32_t a1,
                                         uint32_t a2, uint32_t a3,
                                         uint32_t b0, uint32_t b1) {
    asm volatile(
        "mma.sync.aligned.m16n8k16.row.col.f32.bf16.bf16.f32 "
        "{%0,%1,%2,%3}, {%4,%5,%6,%7}, {%8,%9}, {%0,%1,%2,%3};"
        : "+f"(c[0]), "+f"(c[1]), "+f"(c[2]), "+f"(c[3])
        : "r"(a0), "r"(a1), "r"(a2), "r"(a3), "r"(b0), "r"(b1));
}
// split fp32 pair -> bf16 hi/lo pairs at byte offset (no swizzle; padded strides)
__device__ __forceinline__ void split2(char* hiB, char* loB, int off, float a, float b) {
    __nv_bfloat16 ah = __float2bfloat16_rn(a);
    __nv_bfloat16 bh = __float2bfloat16_rn(b);
    __nv_bfloat16 al = __float2bfloat16_rn(a - __bfloat162float(ah));
    __nv_bfloat16 bl = __float2bfloat16_rn(b - __bfloat162float(bh));
    *(__nv_bfloat162*)(hiB + off) = __halves2bfloat162(ah, bh);
    *(__nv_bfloat162*)(loB + off) = __halves2bfloat162(al, bl);
}

__global__ __launch_bounds__(256, 2)
void attn_mma(const float* __restrict__ Q, const float* __restrict__ K,
              const float* __restrict__ V, const int* __restrict__ pad,
              float* __restrict__ outO, float* __restrict__ outW)
{
    extern __shared__ __align__(16) char sm[];
    const int tid  = threadIdx.x;
    const int wid  = tid >> 5;
    const int lane = tid & 31;
    const int bh   = blockIdx.y;
    const int q0   = blockIdx.x * TQ;
    const int b    = bh / Hdim;

    const uint32_t smb = smem_u32(sm);
    float* rowsum = (float*)(sm + RS_B);
    float* invp   = (float*)(sm + INV_B);
    int*   pmp    = (int*)(sm + PM_B);
    float* eb     = (float*)(sm + EB_B);

    const float* Qb = Q + ((size_t)bh * Sdim + q0) * Ddim;
    const float* Kb = K + (size_t)bh * Sdim * Ddim;
    const float* Vb = V + (size_t)bh * Sdim * Ddim;
    const int*   pb = pad + (size_t)b * Sdim;
    float* Wb = outW + ((size_t)bh * Sdim + q0) * Sdim;   // [TQ][Sdim]

    // ---- stage Q tile (split bf16 hi/lo), zero rowsums ----
    for (int i = tid; i < TQ * Ddim / 4; i += 256) {   // 1024 float4
        int q = i >> 4, db = (i & 15) * 4;
        float4 v = *(const float4*)(Qb + (size_t)q * Ddim + db);
        int base = q * QK_STR + db * 2;
        split2(sm + QS_HI_B, sm + QS_LO_B, base,     v.x, v.y);
        split2(sm + QS_HI_B, sm + QS_LO_B, base + 4, v.z, v.w);
    }
    if (tid < TQ) rowsum[tid] = 0.f;

    // warp tiles
    const int wq = wid & 3;          // q-group: 16 rows at wq*16
    const int wk = wid >> 2;         // QK: k-group, 64 cols at wk*64
    const int wd = wk;               // PV: d-group, 32 cols at wd*32

    // ldmatrix lane->address components (derived from PTX fragment layouts)
    const int arow  = lane & 15;                       // A: rows 0..15
    const int apart = (lane >> 4) * 16;                // A: k-half select (bytes)
    const int brow  = (lane & 7) + ((lane >> 4) << 3); // B (QK, no trans)
    const int bpart = ((lane >> 3) & 1) * 16;
    const int vrow  = (lane & 7) + (((lane >> 3) & 1) << 3);  // B (PV, trans)
    const int vpart = (lane >> 4) * 16;

    const int rlo   = wq * 16 + (lane >> 2);   // this thread's low output row
    float rs_lo = 0.f, rs_hi = 0.f;

    // ======================= QK^T + exp phase =======================
    for (int s = 0; s < NSLAB; ++s) {
        const int k0 = s * NK;
        __syncthreads();  // prev slab's frag reads + EBUF copy done

        // stage K slab (split bf16 hi/lo) + padding mask
        for (int i = tid; i < NK * Ddim / 4; i += 256) {   // 2048 float4
            int k = i >> 4, db = (i & 15) * 4;
            float4 v = *(const float4*)(Kb + (size_t)(k0 + k) * Ddim + db);
            int base = k * QK_STR + db * 2;
            split2(sm + KS_HI_B, sm + KS_LO_B, base,     v.x, v.y);
            split2(sm + KS_HI_B, sm + KS_LO_B, base + 4, v.z, v.w);
        }
        if (tid < NK) pmp[tid] = pb[k0 + tid];
        __syncthreads();

        float c[8][4];
        #pragma unroll
        for (int n = 0; n < 8; ++n)
            #pragma unroll
            for (int j = 0; j < 4; ++j) c[n][j] = 0.f;

        // 3 passes: hiQ*hiK, hiQ*loK, loQ*hiK
        #pragma unroll
        for (int p = 0; p < 3; ++p) {
            const uint32_t Abuf = smb + ((p < 2) ? QS_HI_B : QS_LO_B);
            const uint32_t Bbuf = smb + ((p == 1) ? KS_LO_B : KS_HI_B);
            #pragma unroll
            for (int ks = 0; ks < 4; ++ks) {
                uint32_t a0, a1, a2, a3;
                ldsm4(Abuf + (wq * 16 + arow) * QK_STR + ks * 32 + apart, a0, a1, a2, a3);
                #pragma unroll
                for (int nt2 = 0; nt2 < 4; ++nt2) {
                    uint32_t b0, b1, b2, b3;
                    ldsm4(Bbuf + (wk * 64 + nt2 * 16 + brow) * QK_STR + ks * 32 + bpart,
                          b0, b1, b2, b3);
                    mma16816(c[2 * nt2],     a0, a1, a2, a3, b0, b1);
                    mma16816(c[2 * nt2 + 1], a0, a1, a2, a3, b2, b3);
                }
            }
        }

        // epilogue: scale, faithful mask ((future+pad)==1), exp, rowsum, stage e
        const int qglo = q0 + rlo, qghi = qglo + 8;
        #pragma unroll
        for (int nt = 0; nt < 8; ++nt) {
            const int col = wk * 64 + nt * 8 + (lane & 3) * 2;
            const int kg  = k0 + col;
            const int p0 = pmp[col], p1 = pmp[col + 1];
            float e0 = (((kg     > qglo) + p0) == 1) ? 0.f : __expf(c[nt][0] * 0.125f);
            float e1 = (((kg + 1 > qglo) + p1) == 1) ? 0.f : __expf(c[nt][1] * 0.125f);
            float e2 = (((kg     > qghi) + p0) == 1) ? 0.f : __expf(c[nt][2] * 0.125f);
            float e3 = (((kg + 1 > qghi) + p1) == 1) ? 0.f : __expf(c[nt][3] * 0.125f);
            rs_lo += e0 + e1;
            rs_hi += e2 + e3;
            *(float2*)&eb[rlo * EB_STR + col]       = make_float2(e0, e1);
            *(float2*)&eb[(rlo + 8) * EB_STR + col] = make_float2(e2, e3);
        }
        __syncthreads();

        // coalesced store of unnormalized e to W
        for (int i = tid; i < TQ * NK / 4; i += 256) {   // 2048 float4
            int q = i >> 5, cb = (i & 31) * 4;
            *(float4*)&Wb[(size_t)q * Sdim + k0 + cb] = *(float4*)&eb[q * EB_STR + cb];
        }
    }

    // ---- rowsums -> inv ----
    rs_lo += __shfl_xor_sync(0xffffffffu, rs_lo, 1);
    rs_lo += __shfl_xor_sync(0xffffffffu, rs_lo, 2);
    rs_hi += __shfl_xor_sync(0xffffffffu, rs_hi, 1);
    rs_hi += __shfl_xor_sync(0xffffffffu, rs_hi, 2);
    if ((lane & 3) == 0) {
        atomicAdd(&rowsum[rlo], rs_lo);
        atomicAdd(&rowsum[rlo + 8], rs_hi);
    }
    __syncthreads();
    if (tid < TQ) invp[tid] = 1.0f / rowsum[tid];

    // ======================= P @ V phase =======================
    float co[4][4];
    #pragma unroll
    for (int n = 0; n < 4; ++n)
        #pragma unroll
        for (int j = 0; j < 4; ++j) co[n][j] = 0.f;

    for (int s = 0; s < NSLAB; ++s) {
        const int k0 = s * NK;
        __syncthreads();  // prev slab frag reads done; also orders invp on s==0

        // stage V slab (split bf16 hi/lo) into KS region, [k][d] row-major
        for (int i = tid; i < NK * Ddim / 4; i += 256) {
            int k = i >> 4, db = (i & 15) * 4;
            float4 v = *(const float4*)(Vb + (size_t)(k0 + k) * Ddim + db);
            int base = k * QK_STR + db * 2;
            split2(sm + KS_HI_B, sm + KS_LO_B, base,     v.x, v.y);
            split2(sm + KS_HI_B, sm + KS_LO_B, base + 4, v.z, v.w);
        }
        // stage P: read e (L2-hot), normalize, write final W, split bf16 hi/lo
        for (int i = tid; i < TQ * NK / 4; i += 256) {
            int q = i >> 5, kb = (i & 31) * 4;
            float* gw = Wb + (size_t)q * Sdim + k0 + kb;
            float4 e = *(float4*)gw;
            const float iv = invp[q];
            e.x *= iv; e.y *= iv; e.z *= iv; e.w *= iv;
            *(float4*)gw = e;
            int base = q * PS_STR + kb * 2;
            split2(sm + PS_HI_B, sm + PS_LO_B, base,     e.x, e.y);
            split2(sm + PS_HI_B, sm + PS_LO_B, base + 4, e.z, e.w);
        }
        __syncthreads();

        // 3 passes: hiP*hiV, hiP*loV, loP*hiV
        #pragma unroll
        for (int p = 0; p < 3; ++p) {
            const uint32_t Abuf = smb + ((p < 2) ? PS_HI_B : PS_LO_B);
            const uint32_t Bbuf = smb + ((p == 1) ? KS_LO_B : KS_HI_B);
            #pragma unroll
            for (int ks = 0; ks < 8; ++ks) {
                uint32_t a0, a1, a2, a3;
                ldsm4(Abuf + (wq * 16 + arow) * PS_STR + ks * 32 + apart, a0, a1, a2, a3);
                #pragma unroll
                for (int nt2 = 0; nt2 < 2; ++nt2) {
                    uint32_t b0, b1, b2, b3;
                    ldsm4t(Bbuf + (ks * 16 + vrow) * QK_STR + (wd * 32 + nt2 * 16) * 2 + vpart,
                           b0, b1, b2, b3);
                    mma16816(co[2 * nt2],     a0, a1, a2, a3, b0, b1);
                    mma16816(co[2 * nt2 + 1], a0, a1, a2, a3, b2, b3);
                }
            }
        }
    }

    // ---- O store (P was pre-normalized, frags are final) ----
    #pragma unroll
    for (int nt = 0; nt < 4; ++nt) {
        const int col = wd * 32 + nt * 8 + (lane & 3) * 2;
        const size_t r0o = ((size_t)bh * Sdim + q0 + rlo) * Ddim + col;
        const size_t r1o = ((size_t)bh * Sdim + q0 + rlo + 8) * Ddim + col;
        *(float2*)&outO[r0o] = make_float2(co[nt][0], co[nt][1]);
        *(float2*)&outO[r1o] = make_float2(co[nt][2], co[nt][3]);
    }
}

extern "C" void kernel_launch(void* const* d_in, const int* in_sizes, int n_in,
                              void* d_out, int out_size)
{
    const float* Q   = (const float*)d_in[0];
    const float* K   = (const float*)d_in[1];
    const float* V   = (const float*)d_in[2];
    const int*   pad = (const int*)d_in[3];

    const long long nres = (long long)BHdim * Sdim * Ddim;   // 8,388,608
    float* outO = (float*)d_out;
    float* outW = outO + nres;   // out = (result, attention_weights)

    cudaFuncSetAttribute(attn_mma, cudaFuncAttributeMaxDynamicSharedMemorySize, SMEM_TOTAL);

    dim3 grid(Sdim / TQ, BHdim);
    attn_mma<<<grid, 256, SMEM_TOTAL>>>(Q, K, V, pad, outO, outW);
}